// round 14
// baseline (speedup 1.0000x reference)
#include <cuda_runtime.h>
#include <math.h>
#include <stdint.h>

// Problem constants
#define HH 512
#define II 1024
#define EE 8
#define TT 8192
#define TP 16384

#define BM 256
#define BK 32
#define MAXT 72             // max 256-row m-tiles: 16384/256 + 7 = 71

// smem layout (bytes)
#define ASTR 36             // floats per A row (BK + 4)
#define BSTR 136            // floats per B k-row (128 + 8)
#define ABYTES (BM*ASTR*4)      // 36864
#define BBYTES (BK*BSTR*4)      // 17408
#define SM_TOK 0                // 256 ints
#define SM_A   1024
#define SM_B   (SM_A + 2*ABYTES)            // 74752
#define SM_TOT (SM_B + 2*BBYTES)            // 109568

#define NS1 (HH/BK)         // 16
#define NS2 (II/BK)         // 32

// ---------------- device-global scratch ----------------
__device__ float g_hinter[(size_t)TP * II];   // 64MB (tf32-rounded by gemm1)
__device__ int   g_perm[TP];
__device__ int   g_off[EE + 1];
__device__ int   g_mt_e[MAXT];
__device__ int   g_mt_r[MAXT];
__device__ int   g_nmt;

// ---------------- helpers ----------------
__device__ __forceinline__ float rnaf(float f) {
    uint32_t r;
    asm("cvt.rna.tf32.f32 %0, %1;" : "=r"(r) : "f"(f));
    return __uint_as_float(r);
}
__device__ __forceinline__ void mma_tf32(float* d, const uint32_t* a, uint32_t b0, uint32_t b1) {
    asm volatile(
        "mma.sync.aligned.m16n8k8.row.col.f32.tf32.tf32.f32 "
        "{%0,%1,%2,%3}, {%4,%5,%6,%7}, {%8,%9}, {%0,%1,%2,%3};\n"
        : "+f"(d[0]), "+f"(d[1]), "+f"(d[2]), "+f"(d[3])
        : "r"(a[0]), "r"(a[1]), "r"(a[2]), "r"(a[3]), "r"(b0), "r"(b1));
}
__device__ __forceinline__ float silu(float g) { return g / (1.0f + expf(-g)); }

// ---------------- routing ----------------
__global__ void route_kernel(const int* __restrict__ eidx) {
    __shared__ int s_cnt[EE], s_cur[EE], s_off[EE];
    int tid = threadIdx.x;
    if (tid < EE) { s_cnt[tid] = 0; s_cur[tid] = 0; }
    __syncthreads();
    for (int i = tid; i < TP; i += blockDim.x) atomicAdd(&s_cnt[eidx[i]], 1);
    __syncthreads();
    if (tid == 0) {
        int acc = 0, nm = 0;
        for (int e = 0; e < EE; e++) {
            s_off[e] = acc; g_off[e] = acc;
            for (int r = 0; r < s_cnt[e]; r += BM) { g_mt_e[nm] = e; g_mt_r[nm] = r; nm++; }
            acc += s_cnt[e];
        }
        g_off[EE] = acc; g_nmt = nm;
    }
    __syncthreads();
    for (int i = tid; i < TP; i += blockDim.x) {
        int e = eidx[i];
        int p = atomicAdd(&s_cur[e], 1);
        g_perm[s_off[e] + p] = i;
    }
}

// ======================= GEMM1: x @ w13 (+fused SwiGLU) -> g_hinter =======================
// grid (MAXT, II/64). 512 threads. B tile: 64 gate + 64 up cols interleaved by 8.
__global__ __launch_bounds__(512, 1) void gemm1_kernel(const float* __restrict__ x,
                                                       const float* __restrict__ w13) {
    extern __shared__ __align__(16) char smem[];
    const int mtile = blockIdx.x;
    if (mtile >= g_nmt) return;
    const int chunk = blockIdx.y;
    const int e = g_mt_e[mtile], r0 = g_mt_r[mtile];
    const int off = g_off[e], ne = g_off[e + 1] - off;
    const int rows = min(BM, ne - r0);

    const int tid = threadIdx.x, wid = tid >> 5, lane = tid & 31;
    const int g = lane >> 2, t4 = lane & 3;
    const int mw = wid & 3, nw = wid >> 2;
    const int wrow = mw * 64, nb = nw * 32;

    int* stok = (int*)(smem + SM_TOK);
    if (tid < BM) {
        int m = r0 + tid;
        stok[tid] = (m < ne) ? (g_perm[off + m] >> 1) : 0;  // clamp; invalid rows discarded later
    }
    __syncthreads();

    const float* wb = w13 + (size_t)e * HH * (2 * II);
    const int n0p = chunk * 64;

    // staging geometry (512 threads)
    const int f = tid & 7;                  // A: float4 slot within row
    const int rowb = tid >> 6;              // A: row base 0..7? no:
    // A tile 256 rows x 8 slots = 2048 float4 / 512 threads = 4 each
    const int arow = tid >> 3;              // 0..63, rows arow + 64*j
    const int c4 = tid & 31;                // B: float4 col
    const int kkb = tid >> 5;               // B: k-row base 0..15, rows kkb + 16*j
    (void)rowb;
    const int c0 = c4 * 4;
    const int w16 = c0 & 15, pg = c0 >> 4;
    const int bcol = (w16 < 8) ? (n0p + pg * 8 + w16) : (II + n0p + pg * 8 + (w16 - 8));

    const float* aSrc[4];
#pragma unroll
    for (int j = 0; j < 4; j++)
        aSrc[j] = x + (size_t)stok[arow + 64 * j] * HH + f * 4;
    const float* bSrc = wb + (size_t)kkb * (2 * II) + bcol;
    const int aOff0 = arow * ASTR + f * 4;      // +64*ASTR per j
    const int bOff0 = kkb * BSTR + c0;          // +16*BSTR per j

    float4 pa[4], pb[2];
    auto ldg = [&](int s) {
        const int k0 = s * BK;
#pragma unroll
        for (int j = 0; j < 4; j++)
            pa[j] = *(const float4*)(aSrc[j] + k0);
#pragma unroll
        for (int j = 0; j < 2; j++)
            pb[j] = *(const float4*)(bSrc + (size_t)(k0 + 16 * j) * (2 * II));
    };
    auto sts = [&](int s) {
        float* A = (float*)(smem + SM_A + (s & 1) * ABYTES);
        float* B = (float*)(smem + SM_B + (s & 1) * BBYTES);
#pragma unroll
        for (int j = 0; j < 4; j++) {
            float4 ra = make_float4(rnaf(pa[j].x), rnaf(pa[j].y), rnaf(pa[j].z), rnaf(pa[j].w));
            *(float4*)(A + aOff0 + j * 64 * ASTR) = ra;
        }
#pragma unroll
        for (int j = 0; j < 2; j++) {
            float4 rb = make_float4(rnaf(pb[j].x), rnaf(pb[j].y), rnaf(pb[j].z), rnaf(pb[j].w));
            *(float4*)(B + bOff0 + j * 16 * BSTR) = rb;
        }
    };

    float acc[4][4][4];
#pragma unroll
    for (int a = 0; a < 4; a++)
#pragma unroll
        for (int b = 0; b < 4; b++)
#pragma unroll
            for (int q = 0; q < 4; q++) acc[a][b][q] = 0.0f;

    ldg(0); sts(0); ldg(1);
    __syncthreads();

    for (int s = 0; s < NS1; s++) {
        const uint32_t* As = (const uint32_t*)(smem + SM_A + (s & 1) * ABYTES);
        const uint32_t* Bs = (const uint32_t*)(smem + SM_B + (s & 1) * BBYTES);
#pragma unroll
        for (int kh = 0; kh < 4; kh++) {
            uint32_t a[4][4];
#pragma unroll
            for (int mt = 0; mt < 4; mt++) {
                int r = wrow + mt * 16 + g;
                a[mt][0] = As[r * ASTR + kh * 8 + t4];
                a[mt][1] = As[(r + 8) * ASTR + kh * 8 + t4];
                a[mt][2] = As[r * ASTR + kh * 8 + t4 + 4];
                a[mt][3] = As[(r + 8) * ASTR + kh * 8 + t4 + 4];
            }
            uint32_t b[4][2];
#pragma unroll
            for (int nt = 0; nt < 4; nt++) {
                b[nt][0] = Bs[(kh * 8 + t4) * BSTR + nb + nt * 8 + g];
                b[nt][1] = Bs[(kh * 8 + t4 + 4) * BSTR + nb + nt * 8 + g];
            }
#pragma unroll
            for (int nt = 0; nt < 4; nt++)
#pragma unroll
                for (int mt = 0; mt < 4; mt++)
                    mma_tf32(acc[mt][nt], a[mt], b[nt][0], b[nt][1]);
        }
        if (s + 1 < NS1) {
            sts(s + 1);
            if (s + 2 < NS1) ldg(s + 2);
        }
        __syncthreads();
    }

    // epilogue: fused SwiGLU (nt pairs (0,1),(2,3) are gate/up of the same logical cols)
#pragma unroll
    for (int mt = 0; mt < 4; mt++) {
        int r = wrow + mt * 16 + g;
#pragma unroll
        for (int pp = 0; pp < 2; pp++) {
            int hc = n0p + (2 * nw + pp) * 8 + 2 * t4;
            const float* ga = acc[mt][2 * pp];
            const float* ua = acc[mt][2 * pp + 1];
            if (r < rows) {
                float2 h;
                h.x = rnaf(silu(ga[0]) * ua[0]);
                h.y = rnaf(silu(ga[1]) * ua[1]);
                *(float2*)(g_hinter + (size_t)(off + r0 + r) * II + hc) = h;
            }
            if (r + 8 < rows) {
                float2 h;
                h.x = rnaf(silu(ga[2]) * ua[2]);
                h.y = rnaf(silu(ga[3]) * ua[3]);
                *(float2*)(g_hinter + (size_t)(off + r0 + r + 8) * II + hc) = h;
            }
        }
    }
}

// ======================= GEMM2: h_inter @ w2 -> scattered out =======================
// grid (MAXT, HH/128). 512 threads.
__global__ __launch_bounds__(512, 1) void gemm2_kernel(const float* __restrict__ w2,
                                                       float* __restrict__ out) {
    extern __shared__ __align__(16) char smem[];
    const int mtile = blockIdx.x;
    if (mtile >= g_nmt) return;
    const int chunk = blockIdx.y;
    const int e = g_mt_e[mtile], r0 = g_mt_r[mtile];
    const int off = g_off[e], ne = g_off[e + 1] - off;
    const int rows = min(BM, ne - r0);

    const int tid = threadIdx.x, wid = tid >> 5, lane = tid & 31;
    const int g = lane >> 2, t4 = lane & 3;
    const int mw = wid & 3, nw = wid >> 2;
    const int wrow = mw * 64, nb = nw * 32;

    const float* wb = w2 + (size_t)e * II * HH;
    const float* abase = g_hinter + (size_t)(off + r0) * II;
    const int n0 = chunk * 128;

    const int f = tid & 7;
    const int arow = tid >> 3;              // 0..63
    const int c4 = tid & 31;
    const int kkb = tid >> 5;               // 0..15

    const float* aSrc[4];
#pragma unroll
    for (int j = 0; j < 4; j++) {
        int row = arow + 64 * j;
        aSrc[j] = abase + (size_t)((row < rows) ? row : 0) * II + f * 4;
    }
    const float* bSrc = wb + (size_t)kkb * HH + n0 + c4 * 4;
    const int aOff0 = arow * ASTR + f * 4;
    const int bOff0 = kkb * BSTR + c4 * 4;

    float4 pa[4], pb[2];
    auto ldg = [&](int s) {
        const int k0 = s * BK;
#pragma unroll
        for (int j = 0; j < 4; j++)
            pa[j] = *(const float4*)(aSrc[j] + k0);
#pragma unroll
        for (int j = 0; j < 2; j++)
            pb[j] = *(const float4*)(bSrc + (size_t)(k0 + 16 * j) * HH);
    };
    auto sts = [&](int s) {
        float* A = (float*)(smem + SM_A + (s & 1) * ABYTES);
        float* B = (float*)(smem + SM_B + (s & 1) * BBYTES);
#pragma unroll
        for (int j = 0; j < 4; j++)
            *(float4*)(A + aOff0 + j * 64 * ASTR) = pa[j];   // hinter already tf32-rounded
#pragma unroll
        for (int j = 0; j < 2; j++) {
            float4 rb = make_float4(rnaf(pb[j].x), rnaf(pb[j].y), rnaf(pb[j].z), rnaf(pb[j].w));
            *(float4*)(B + bOff0 + j * 16 * BSTR) = rb;
        }
    };

    float acc[4][4][4];
#pragma unroll
    for (int a = 0; a < 4; a++)
#pragma unroll
        for (int b = 0; b < 4; b++)
#pragma unroll
            for (int q = 0; q < 4; q++) acc[a][b][q] = 0.0f;

    ldg(0); sts(0); ldg(1);
    __syncthreads();

    for (int s = 0; s < NS2; s++) {
        const uint32_t* As = (const uint32_t*)(smem + SM_A + (s & 1) * ABYTES);
        const uint32_t* Bs = (const uint32_t*)(smem + SM_B + (s & 1) * BBYTES);
#pragma unroll
        for (int kh = 0; kh < 4; kh++) {
            uint32_t a[4][4];
#pragma unroll
            for (int mt = 0; mt < 4; mt++) {
                int r = wrow + mt * 16 + g;
                a[mt][0] = As[r * ASTR + kh * 8 + t4];
                a[mt][1] = As[(r + 8) * ASTR + kh * 8 + t4];
                a[mt][2] = As[r * ASTR + kh * 8 + t4 + 4];
                a[mt][3] = As[(r + 8) * ASTR + kh * 8 + t4 + 4];
            }
            uint32_t b[4][2];
#pragma unroll
            for (int nt = 0; nt < 4; nt++) {
                b[nt][0] = Bs[(kh * 8 + t4) * BSTR + nb + nt * 8 + g];
                b[nt][1] = Bs[(kh * 8 + t4 + 4) * BSTR + nb + nt * 8 + g];
            }
#pragma unroll
            for (int nt = 0; nt < 4; nt++)
#pragma unroll
                for (int mt = 0; mt < 4; mt++)
                    mma_tf32(acc[mt][nt], a[mt], b[nt][0], b[nt][1]);
        }
        if (s + 1 < NS2) {
            sts(s + 1);
            if (s + 2 < NS2) ldg(s + 2);
        }
        __syncthreads();
    }

    // epilogue: scatter rows via perm
#pragma unroll
    for (int mt = 0; mt < 4; mt++) {
        int r = wrow + mt * 16 + g;
        int pair0 = (r < rows) ? g_perm[off + r0 + r] : -1;
        int pair1 = (r + 8 < rows) ? g_perm[off + r0 + r + 8] : -1;
#pragma unroll
        for (int nt = 0; nt < 4; nt++) {
            int col = n0 + nb + nt * 8 + 2 * t4;
            if (pair0 >= 0)
                *(float2*)(out + (size_t)pair0 * HH + col) =
                    make_float2(acc[mt][nt][0], acc[mt][nt][1]);
            if (pair1 >= 0)
                *(float2*)(out + (size_t)pair1 * HH + col) =
                    make_float2(acc[mt][nt][2], acc[mt][nt][3]);
        }
    }
}

// ---------------- launch ----------------
extern "C" void kernel_launch(void* const* d_in, const int* in_sizes, int n_in,
                              void* d_out, int out_size) {
    const float* x    = (const float*)d_in[0];
    const int*   eidx = (const int*)d_in[1];
    const float* w13  = (const float*)d_in[2];
    const float* w2   = (const float*)d_in[3];
    float* out = (float*)d_out;

    cudaFuncSetAttribute(gemm1_kernel, cudaFuncAttributeMaxDynamicSharedMemorySize, SM_TOT);
    cudaFuncSetAttribute(gemm2_kernel, cudaFuncAttributeMaxDynamicSharedMemorySize, SM_TOT);

    route_kernel<<<1, 1024>>>(eidx);
    gemm1_kernel<<<dim3(MAXT, II / 64), 512, SM_TOT>>>(x, w13);
    gemm2_kernel<<<dim3(MAXT, HH / 128), 512, SM_TOT>>>(w2, out);
}